// round 9
// baseline (speedup 1.0000x reference)
#include <cuda_runtime.h>
#include <cuda_bf16.h>
#include <math.h>

// ---------------- problem dims (fixed) ----------------
constexpr int L_  = 4;
constexpr int B_  = 2;
constexpr int S_  = 1024;
constexpr int E_  = 1024;
constexpr int H_  = 16;
constexpr int HD_ = 64;
constexpr int FF_ = 6 * E_;     // 6144
constexpr int V_  = 32000;
constexpr int T_  = B_ * S_;    // 2048 tokens

// ---------------- device scratch (no allocs allowed) ----------------
__device__ float g_h [T_ * E_];            // residual stream
__device__ float g_z [T_ * E_];            // LN output
__device__ float g_q [T_ * E_];            // [B,H,S,HD]
__device__ float g_k [T_ * E_];
__device__ float g_v [T_ * E_];
__device__ float g_oc[T_ * E_];            // concat-heads attn output [T,E]
__device__ float g_sc[(long)B_ * H_ * S_ * S_]; // attention scores
__device__ float g_ff[(long)T_ * FF_];     // FFN hidden

// ---------------- cp.async helpers ----------------
__device__ __forceinline__ void cp_async16(void* smem_dst, const void* gmem_src) {
    unsigned sm = (unsigned)__cvta_generic_to_shared(smem_dst);
    asm volatile("cp.async.cg.shared.global [%0], [%1], 16;\n" :: "r"(sm), "l"(gmem_src));
}
__device__ __forceinline__ void cp_async_commit() {
    asm volatile("cp.async.commit_group;\n" ::: "memory");
}
__device__ __forceinline__ void cp_async_wait0() {
    asm volatile("cp.async.wait_group 0;\n" ::: "memory");
}

// ---------------- generic batched tiled GEMM (double-buffered, vectorized) ----
// C = alpha * A @ (TRB ? B^T : B)  (+R if EPI==1, gelu if EPI==2)
// batch offset: o1 = bz/Hd, o2 = bz%Hd ; ptr += o1*s1 + o2*s2
// CSKIP: early-exit tiles fully above the causal diagonal (scores GEMM).
// CKLIM: truncate K to rowBase+BM (A columns beyond are exact zeros; AV GEMM).
// SWAPXY: blockIdx.x -> M tile, blockIdx.y -> N tile (weight-stationary L2 reuse).
// __launch_bounds__(256,2): cap regs at 128 -> guaranteed 2 CTAs/SM so the
// co-resident CTA hides barrier + fill latency.
template<int BM, int BN, int BK, int TM, int TN, bool TRB, int EPI,
         bool CSKIP = false, bool CKLIM = false, bool SWAPXY = false>
__global__ void __launch_bounds__(256, 2)
gemm_k(const float* __restrict__ A, const float* __restrict__ B,
       const float* __restrict__ R, float* __restrict__ C,
       int K, int lda, int ldb, int ldc,
       long sA1, long sA2, long sB1, long sB2, long sC1, long sC2,
       int Hd, float alpha)
{
    constexpr int THREADS = (BM / TM) * (BN / TN);
    static_assert(THREADS == 256, "block must be 256 threads");
    constexpr int KV = BK / 4;                    // float4s along K
    constexpr int AR = (BM * BK) / (4 * THREADS); // A float4s per thread
    constexpr int BR = (BN * BK) / (4 * THREADS); // B float4s per thread
    static_assert(AR >= 1 && BR >= 1, "tile too small for vector loads");

    const long rowBase = (long)(SWAPXY ? blockIdx.x : blockIdx.y) * BM;
    const long colBase = (long)(SWAPXY ? blockIdx.y : blockIdx.x) * BN;

    // causal tile skip: every (row,col) in this tile has col > row -> masked.
    if (CSKIP && colBase > rowBase + (BM - 1)) return;

    __shared__ __align__(16) float As[2][BK][BM + 4];
    __shared__ __align__(16) float Bs[2][BK][BN + 4];

    const long o1 = blockIdx.z / Hd;
    const long o2 = blockIdx.z % Hd;
    A += o1 * sA1 + o2 * sA2;
    B += o1 * sB1 + o2 * sB2;
    const long cOff = o1 * sC1 + o2 * sC2;
    C += cOff;
    if (EPI == 1) R += cOff;

    const int tid = threadIdx.x;
    const int tx  = tid % (BN / TN);
    const int ty  = tid / (BN / TN);

    float acc[TM][TN] = {};

    auto load_a_regs = [&](int k0, float4 (&fa)[AR]) {
        #pragma unroll
        for (int r = 0; r < AR; r++) {
            int i  = tid + r * THREADS;
            int m  = i / KV;
            int kv = i % KV;
            fa[r] = *reinterpret_cast<const float4*>(
                &A[(rowBase + m) * (long)lda + k0 + kv * 4]);
        }
    };
    auto store_a_smem = [&](int buf, const float4 (&fa)[AR]) {
        #pragma unroll
        for (int r = 0; r < AR; r++) {
            int i  = tid + r * THREADS;
            int m  = i / KV;
            int kv = i % KV;
            As[buf][kv * 4 + 0][m] = fa[r].x;
            As[buf][kv * 4 + 1][m] = fa[r].y;
            As[buf][kv * 4 + 2][m] = fa[r].z;
            As[buf][kv * 4 + 3][m] = fa[r].w;
        }
    };
    // transposed-B register path (scores GEMM only)
    auto load_b_regs = [&](int k0, float4 (&fb)[BR]) {
        #pragma unroll
        for (int r = 0; r < BR; r++) {
            int i  = tid + r * THREADS;
            int n  = i / KV;
            int kv = i % KV;
            fb[r] = *reinterpret_cast<const float4*>(
                &B[(colBase + n) * (long)ldb + k0 + kv * 4]);
        }
    };
    auto store_b_smem = [&](int buf, const float4 (&fb)[BR]) {
        #pragma unroll
        for (int r = 0; r < BR; r++) {
            int i  = tid + r * THREADS;
            int n  = i / KV;
            int kv = i % KV;
            Bs[buf][kv * 4 + 0][n] = fb[r].x;
            Bs[buf][kv * 4 + 1][n] = fb[r].y;
            Bs[buf][kv * 4 + 2][n] = fb[r].z;
            Bs[buf][kv * 4 + 3][n] = fb[r].w;
        }
    };
    // non-transposed B: direct gmem->smem async copy
    auto issue_b_cp = [&](int k0, int buf) {
        #pragma unroll
        for (int r = 0; r < BR; r++) {
            int i  = tid + r * THREADS;
            int kk = i / (BN / 4);
            int nv = i % (BN / 4);
            cp_async16(&Bs[buf][kk][nv * 4],
                       &B[(long)(k0 + kk) * ldb + colBase + nv * 4]);
        }
    };
    auto compute = [&](int buf) {
        #pragma unroll
        for (int kk = 0; kk < BK; kk++) {
            float ra[TM], rb[TN];
            #pragma unroll
            for (int i = 0; i < TM / 4; i++)
                *reinterpret_cast<float4*>(&ra[i * 4]) =
                    *reinterpret_cast<const float4*>(&As[buf][kk][ty * TM + i * 4]);
            #pragma unroll
            for (int j = 0; j < TN / 4; j++)
                *reinterpret_cast<float4*>(&rb[j * 4]) =
                    *reinterpret_cast<const float4*>(&Bs[buf][kk][tx * TN + j * 4]);
            #pragma unroll
            for (int i = 0; i < TM; i++)
                #pragma unroll
                for (int j = 0; j < TN; j++)
                    acc[i][j] += ra[i] * rb[j];
        }
    };

    // causal K truncation: att[row][t] == 0 exactly for t > row, so columns of A
    // beyond rowBase+BM contribute exact zeros -> skip them.
    int Keff = K;
    if (CKLIM) {
        long lim = rowBase + BM;
        if (lim < Keff) Keff = (int)lim;
    }

    // ---- prologue ----
    if (!TRB) {
        issue_b_cp(0, 0);
        cp_async_commit();
    }
    {
        float4 fa[AR];
        load_a_regs(0, fa);
        store_a_smem(0, fa);
        if (TRB) {
            float4 fb[BR];
            load_b_regs(0, fb);
            store_b_smem(0, fb);
        }
    }
    if (!TRB) cp_async_wait0();
    __syncthreads();

    // ---- pipelined mainloop ----
    int buf = 0;
    const int nIter = Keff / BK;
    for (int it = 0; it < nIter; it++) {
        const bool more = (it + 1 < nIter);
        float4 fa[AR], fb[BR];
        if (more) {
            if (!TRB) {               // async fill of the alternate buffer
                issue_b_cp((it + 1) * BK, buf ^ 1);
                cp_async_commit();
            }
            load_a_regs((it + 1) * BK, fa);
            if (TRB) load_b_regs((it + 1) * BK, fb);
        }
        compute(buf);
        if (more) {
            store_a_smem(buf ^ 1, fa);
            if (TRB) store_b_smem(buf ^ 1, fb);
        }
        if (!TRB) cp_async_wait0();
        __syncthreads();
        buf ^= 1;
    }

    // ---- epilogue ----
    #pragma unroll
    for (int i = 0; i < TM; i++) {
        long row = rowBase + ty * TM + i;
        #pragma unroll
        for (int j = 0; j < TN / 4; j++) {
            long col = colBase + tx * TN + j * 4;
            long idx = row * (long)ldc + col;
            float4 v;
            v.x = acc[i][j * 4 + 0] * alpha;
            v.y = acc[i][j * 4 + 1] * alpha;
            v.z = acc[i][j * 4 + 2] * alpha;
            v.w = acc[i][j * 4 + 3] * alpha;
            if (EPI == 1) {
                float4 r = *reinterpret_cast<const float4*>(&R[idx]);
                v.x += r.x; v.y += r.y; v.z += r.z; v.w += r.w;
            }
            if (EPI == 2) {
                v.x = 0.5f * v.x * (1.0f + erff(v.x * 0.70710678118654752f));
                v.y = 0.5f * v.y * (1.0f + erff(v.y * 0.70710678118654752f));
                v.z = 0.5f * v.z * (1.0f + erff(v.z * 0.70710678118654752f));
                v.w = 0.5f * v.w * (1.0f + erff(v.w * 0.70710678118654752f));
            }
            *reinterpret_cast<float4*>(&C[idx]) = v;
        }
    }
}

// ---------------- fused Q/K/V projection: one launch, grid.z selects matrix ----
// Tile 128x64, BK=16, TM=8, TN=4. blockIdx.z = sel*32 + b*H + h.
__global__ void __launch_bounds__(256, 2)
qkv_k(const float* __restrict__ Z,
      const float* __restrict__ WQ, const float* __restrict__ WK,
      const float* __restrict__ WV,
      float* __restrict__ Q, float* __restrict__ Ko, float* __restrict__ Vo)
{
    constexpr int BM = 128, BN = 64, BK = 16, TM = 8, TN = 4;
    constexpr int THREADS = 256;
    constexpr int KV = BK / 4;                    // 4
    constexpr int AR = (BM * BK) / (4 * THREADS); // 2
    constexpr int BR = (BN * BK) / (4 * THREADS); // 1

    __shared__ __align__(16) float As[2][BK][BM + 4];
    __shared__ __align__(16) float Bs[2][BK][BN + 4];

    const int sel = blockIdx.z / (B_ * H_);       // 0=Q 1=K 2=V
    const int bz  = blockIdx.z % (B_ * H_);
    const int b   = bz / H_;
    const int hh  = bz % H_;

    const float* A = Z + (long)b * S_ * E_;
    const float* W = (sel == 0 ? WQ : (sel == 1 ? WK : WV)) + (long)hh * E_ * HD_;
    float*       C = (sel == 0 ? Q  : (sel == 1 ? Ko : Vo)) + (long)bz * S_ * HD_;

    const int tid = threadIdx.x;
    const int tx  = tid % (BN / TN);
    const int ty  = tid / (BN / TN);
    const long rowBase = (long)blockIdx.y * BM;

    float acc[TM][TN] = {};

    auto load_a_regs = [&](int k0, float4 (&fa)[AR]) {
        #pragma unroll
        for (int r = 0; r < AR; r++) {
            int i  = tid + r * THREADS;
            int m  = i / KV;
            int kv = i % KV;
            fa[r] = *reinterpret_cast<const float4*>(
                &A[(rowBase + m) * (long)E_ + k0 + kv * 4]);
        }
    };
    auto store_a_smem = [&](int buf, const float4 (&fa)[AR]) {
        #pragma unroll
        for (int r = 0; r < AR; r++) {
            int i  = tid + r * THREADS;
            int m  = i / KV;
            int kv = i % KV;
            As[buf][kv * 4 + 0][m] = fa[r].x;
            As[buf][kv * 4 + 1][m] = fa[r].y;
            As[buf][kv * 4 + 2][m] = fa[r].z;
            As[buf][kv * 4 + 3][m] = fa[r].w;
        }
    };
    auto issue_b_cp = [&](int k0, int buf) {
        #pragma unroll
        for (int r = 0; r < BR; r++) {
            int i  = tid + r * THREADS;
            int kk = i / (BN / 4);
            int nv = i % (BN / 4);
            cp_async16(&Bs[buf][kk][nv * 4],
                       &W[(long)(k0 + kk) * HD_ + nv * 4]);
        }
    };
    auto compute = [&](int buf) {
        #pragma unroll
        for (int kk = 0; kk < BK; kk++) {
            float ra[TM], rb[TN];
            #pragma unroll
            for (int i = 0; i < TM / 4; i++)
                *reinterpret_cast<float4*>(&ra[i * 4]) =
                    *reinterpret_cast<const float4*>(&As[buf][kk][ty * TM + i * 4]);
            *reinterpret_cast<float4*>(&rb[0]) =
                *reinterpret_cast<const float4*>(&Bs[buf][kk][tx * TN]);
            #pragma unroll
            for (int i = 0; i < TM; i++)
                #pragma unroll
                for (int j = 0; j < TN; j++)
                    acc[i][j] += ra[i] * rb[j];
        }
    };

    // prologue
    issue_b_cp(0, 0);
    cp_async_commit();
    {
        float4 fa[AR];
        load_a_regs(0, fa);
        store_a_smem(0, fa);
    }
    cp_async_wait0();
    __syncthreads();

    int buf = 0;
    constexpr int nIter = E_ / BK;
    for (int it = 0; it < nIter; it++) {
        const bool more = (it + 1 < nIter);
        float4 fa[AR];
        if (more) {
            issue_b_cp((it + 1) * BK, buf ^ 1);
            cp_async_commit();
            load_a_regs((it + 1) * BK, fa);
        }
        compute(buf);
        if (more) store_a_smem(buf ^ 1, fa);
        cp_async_wait0();
        __syncthreads();
        buf ^= 1;
    }

    #pragma unroll
    for (int i = 0; i < TM; i++) {
        long row = rowBase + ty * TM + i;
        float4 v;
        v.x = acc[i][0]; v.y = acc[i][1]; v.z = acc[i][2]; v.w = acc[i][3];
        *reinterpret_cast<float4*>(&C[row * (long)HD_ + tx * TN]) = v;
    }
}

// ---------------- LayerNorm: one block (256 thr) per row of E=1024 ----------------
__global__ void __launch_bounds__(256)
ln_k(const float* __restrict__ x, const float* __restrict__ g,
     const float* __restrict__ b, float* __restrict__ z)
{
    const long row = blockIdx.x;
    const float* xr = x + row * (long)E_;
    const int tid = threadIdx.x;

    float4 v = *reinterpret_cast<const float4*>(&xr[tid * 4]);
    float s  = v.x + v.y + v.z + v.w;
    float s2 = v.x * v.x + v.y * v.y + v.z * v.z + v.w * v.w;

    __shared__ float red0[8], red1[8];
    #pragma unroll
    for (int o = 16; o > 0; o >>= 1) {
        s  += __shfl_xor_sync(0xffffffffu, s,  o);
        s2 += __shfl_xor_sync(0xffffffffu, s2, o);
    }
    if ((tid & 31) == 0) { red0[tid >> 5] = s; red1[tid >> 5] = s2; }
    __syncthreads();
    if (tid == 0) {
        float ts = 0.f, ts2 = 0.f;
        #pragma unroll
        for (int i = 0; i < 8; i++) { ts += red0[i]; ts2 += red1[i]; }
        float mu  = ts / E_;
        float var = ts2 / E_ - mu * mu;
        red0[0] = mu;
        red1[0] = rsqrtf(var + 1e-5f);
    }
    __syncthreads();
    const float mu = red0[0], rstd = red1[0];
    float4 gg = *reinterpret_cast<const float4*>(&g[tid * 4]);
    float4 bb = *reinterpret_cast<const float4*>(&b[tid * 4]);
    float4 o;
    o.x = (v.x - mu) * rstd * gg.x + bb.x;
    o.y = (v.y - mu) * rstd * gg.y + bb.y;
    o.z = (v.z - mu) * rstd * gg.z + bb.z;
    o.w = (v.w - mu) * rstd * gg.w + bb.w;
    *reinterpret_cast<float4*>(&z[row * (long)E_ + tid * 4]) = o;
}

// ---------------- causal masked softmax (UNIFORM control flow) ----------------
// One block per (b,h,s) row. Masked lanes never load (score buffer holds
// garbage above the diagonal from skipped tiles) and never exponentiate.
// Stores truncated to the 64-tile boundary: the AV GEMM (BM=64, CKLIM) only
// reads columns < (s/64+1)*64.
__global__ void __launch_bounds__(256)
softmax_k(float* __restrict__ sc)
{
    const long r = blockIdx.x;
    const int  s = (int)(r % S_);
    const int  tileEnd = ((s >> 6) + 1) << 6;   // (s/64+1)*64
    float* row = sc + r * (long)S_;
    const int tid = threadIdx.x;
    const int t0 = tid * 4;

    float4 v;
    if (t0 <= s) {                // at least one live element -> safe to load
        v = *reinterpret_cast<const float4*>(&row[t0]);
        if (t0 + 1 > s) v.y = -1e30f;
        if (t0 + 2 > s) v.z = -1e30f;
        if (t0 + 3 > s) v.w = -1e30f;
    } else {                      // fully masked: never touch memory
        v = make_float4(-1e30f, -1e30f, -1e30f, -1e30f);
    }
    float mx = fmaxf(fmaxf(v.x, v.y), fmaxf(v.z, v.w));

    __shared__ float red[8];
    #pragma unroll
    for (int o = 16; o > 0; o >>= 1) mx = fmaxf(mx, __shfl_xor_sync(0xffffffffu, mx, o));
    if ((tid & 31) == 0) red[tid >> 5] = mx;
    __syncthreads();
    if (tid == 0) {
        float m = red[0];
        #pragma unroll
        for (int i = 1; i < 8; i++) m = fmaxf(m, red[i]);
        red[0] = m;
    }
    __syncthreads();
    mx = red[0];
    __syncthreads();

    v.x = (t0 + 0 > s) ? 0.f : __expf(v.x - mx);
    v.y = (t0 + 1 > s) ? 0.f : __expf(v.y - mx);
    v.z = (t0 + 2 > s) ? 0.f : __expf(v.z - mx);
    v.w = (t0 + 3 > s) ? 0.f : __expf(v.w - mx);
    float sum = v.x + v.y + v.z + v.w;
    #pragma unroll
    for (int o = 16; o > 0; o >>= 1) sum += __shfl_xor_sync(0xffffffffu, sum, o);
    if ((tid & 31) == 0) red[tid >> 5] = sum;
    __syncthreads();
    if (tid == 0) {
        float t = 0.f;
        #pragma unroll
        for (int i = 0; i < 8; i++) t += red[i];
        red[0] = t;
    }
    __syncthreads();
    const float inv = 1.0f / red[0];
    v.x *= inv; v.y *= inv; v.z *= inv; v.w *= inv;

    if (t0 < tileEnd)             // beyond the tile boundary is never read
        *reinterpret_cast<float4*>(&row[t0]) = v;
}

// ---------------- token + position embedding ----------------
__global__ void __launch_bounds__(256)
embed_k(const int* __restrict__ x, const float* __restrict__ emb,
        const float* __restrict__ pos, float* __restrict__ h)
{
    const long t = blockIdx.x;
    const int sPos = (int)(t % S_);
    const long tok = x[t];
    const int tid = threadIdx.x;
    float4 e = *reinterpret_cast<const float4*>(&emb[tok * E_ + tid * 4]);
    float4 p = *reinterpret_cast<const float4*>(&pos[(long)sPos * E_ + tid * 4]);
    float4 o; o.x = e.x + p.x; o.y = e.y + p.y; o.z = e.z + p.z; o.w = e.w + p.w;
    *reinterpret_cast<float4*>(&h[t * E_ + tid * 4]) = o;
}

// ---------------- host launcher ----------------
extern "C" void kernel_launch(void* const* d_in, const int* in_sizes, int n_in,
                              void* d_out, int out_size)
{
    const int*   x   = (const int*)  d_in[0];
    const float* emb = (const float*)d_in[1];
    const float* pos = (const float*)d_in[2];
    const float* Wq  = (const float*)d_in[3];
    const float* Wk  = (const float*)d_in[4];
    const float* Wv  = (const float*)d_in[5];
    const float* Wo  = (const float*)d_in[6];
    const float* g1  = (const float*)d_in[7];
    const float* b1  = (const float*)d_in[8];
    const float* g2  = (const float*)d_in[9];
    const float* b2  = (const float*)d_in[10];
    const float* W1  = (const float*)d_in[11];
    const float* W2  = (const float*)d_in[12];
    const float* gf  = (const float*)d_in[13];
    const float* bf  = (const float*)d_in[14];
    const float* Wf  = (const float*)d_in[15];
    float* out = (float*)d_out;

    float *h, *z, *q, *k, *v, *oc, *sc, *ff;
    cudaGetSymbolAddress((void**)&h,  g_h);
    cudaGetSymbolAddress((void**)&z,  g_z);
    cudaGetSymbolAddress((void**)&q,  g_q);
    cudaGetSymbolAddress((void**)&k,  g_k);
    cudaGetSymbolAddress((void**)&v,  g_v);
    cudaGetSymbolAddress((void**)&oc, g_oc);
    cudaGetSymbolAddress((void**)&sc, g_sc);
    cudaGetSymbolAddress((void**)&ff, g_ff);

    embed_k<<<T_, 256>>>(x, emb, pos, h);

    const long lyrW  = (long)H_ * E_ * HD_;   // per-layer qkv weight size
    const dim3 gQKV(1, S_ / 128, 3 * B_ * H_);        // fused q/k/v
    const dim3 gSC (S_ / 128, S_ / 128, B_ * H_);     // 128x128 tiles
    const dim3 gAV (1, S_ / 64, B_ * H_);             // 64x64 tiles
    // SWAPXY grids: x = M tiles (fastest) -> weight-stationary L2 reuse
    const dim3 gWO (T_ / 128, E_ / 128, 1);
    const dim3 gUP (T_ / 128, FF_ / 128, 1);
    const dim3 gDN (T_ / 128, E_ / 128, 1);
    const dim3 gLM (T_ / 128, V_ / 128, 1);

    for (int l = 0; l < L_; l++) {
        // ---- LN1 ----
        ln_k<<<T_, 256>>>(h, g1 + (long)l * E_, b1 + (long)l * E_, z);

        // ---- fused QKV: one launch, 768 CTAs ----
        qkv_k<<<gQKV, 256>>>(z,
                             Wq + (long)l * lyrW, Wk + (long)l * lyrW,
                             Wv + (long)l * lyrW, q, k, v);

        // ---- scores = (Q K^T) * HD^-0.5, batched over B*H, causal tile skip ----
        gemm_k<128, 128, 16, 8, 8, true, 0, true, false><<<gSC, 256>>>(
            q, k, nullptr, sc,
            HD_, HD_, HD_, S_,
            (long)S_ * HD_, 0, (long)S_ * HD_, 0, (long)S_ * S_, 0, 1, 0.125f);

        // ---- causal softmax ----
        softmax_k<<<B_ * H_ * S_, 256>>>(sc);

        // ---- O = att @ V, 64-row tiles, causal K truncation, concat layout ----
        gemm_k<64, 64, 16, 4, 4, false, 0, false, true><<<gAV, 256>>>(
            sc, v, nullptr, oc,
            S_, S_, HD_, E_,
            (long)H_ * S_ * S_, (long)S_ * S_,
            (long)H_ * S_ * HD_, (long)S_ * HD_,
            (long)S_ * E_, (long)HD_, H_, 1.0f);

        // ---- h = h + oc @ Wo (SWAPXY) ----
        gemm_k<128, 128, 16, 8, 8, false, 1, false, false, true><<<gWO, 256>>>(
            oc, Wo + (long)l * E_ * E_, h, h,
            E_, E_, E_, E_,
            0, 0, 0, 0, 0, 0, 1, 1.0f);

        // ---- LN2 ----
        ln_k<<<T_, 256>>>(h, g2 + (long)l * E_, b2 + (long)l * E_, z);

        // ---- ff = gelu(z @ W1) (SWAPXY) ----
        gemm_k<128, 128, 16, 8, 8, false, 2, false, false, true><<<gUP, 256>>>(
            z, W1 + (long)l * E_ * FF_, nullptr, ff,
            E_, E_, FF_, FF_,
            0, 0, 0, 0, 0, 0, 1, 1.0f);

        // ---- h = h + ff @ W2 (SWAPXY) ----
        gemm_k<128, 128, 16, 8, 8, false, 1, false, false, true><<<gDN, 256>>>(
            ff, W2 + (long)l * FF_ * E_, h, h,
            FF_, FF_, E_, E_,
            0, 0, 0, 0, 0, 0, 1, 1.0f);
    }

    // ---- final LN + LM head (SWAPXY) ----
    ln_k<<<T_, 256>>>(h, gf, bf, z);
    gemm_k<128, 128, 16, 8, 8, false, 0, false, false, true><<<gLM, 256>>>(
        z, Wf, nullptr, out,
        E_, E_, V_, V_,
        0, 0, 0, 0, 0, 0, 1, 1.0f);
}

// round 12
// speedup vs baseline: 2.1761x; 2.1761x over previous
#include <cuda_runtime.h>
#include <cuda_bf16.h>
#include <math.h>

// ---------------- problem dims (fixed) ----------------
constexpr int L_  = 4;
constexpr int B_  = 2;
constexpr int S_  = 1024;
constexpr int E_  = 1024;
constexpr int H_  = 16;
constexpr int HD_ = 64;
constexpr int FF_ = 6 * E_;     // 6144
constexpr int V_  = 32000;
constexpr int T_  = B_ * S_;    // 2048 tokens

constexpr int PAD_ = 8;         // smem row pad: stride ≡ 8 (mod 32) -> conflict-free fragment LDS

// ---------------- device scratch (no allocs allowed) ----------------
__device__ float g_h [T_ * E_];
__device__ float g_z [T_ * E_];
__device__ float g_q [T_ * E_];
__device__ float g_k [T_ * E_];
__device__ float g_v [T_ * E_];
__device__ float g_oc[T_ * E_];
__device__ float g_sc[(long)B_ * H_ * S_ * S_];
__device__ float g_ff[(long)T_ * FF_];

// ---------------- cp.async helpers ----------------
__device__ __forceinline__ void cp_async16(void* smem_dst, const void* gmem_src) {
    unsigned sm = (unsigned)__cvta_generic_to_shared(smem_dst);
    asm volatile("cp.async.cg.shared.global [%0], [%1], 16;\n" :: "r"(sm), "l"(gmem_src));
}
__device__ __forceinline__ void cp_async_commit() {
    asm volatile("cp.async.commit_group;\n" ::: "memory");
}
__device__ __forceinline__ void cp_async_wait0() {
    asm volatile("cp.async.wait_group 0;\n" ::: "memory");
}

// ---------------- tf32 mma helpers ----------------
__device__ __forceinline__ unsigned f32_tf32(float x) {
    unsigned r;
    asm("cvt.rna.tf32.f32 %0, %1;" : "=r"(r) : "f"(x));
    return r;
}
__device__ __forceinline__ void mma8(float* c,
                                     unsigned a0, unsigned a1, unsigned a2, unsigned a3,
                                     unsigned b0, unsigned b1) {
    asm("mma.sync.aligned.m16n8k8.row.col.f32.tf32.tf32.f32 "
        "{%0,%1,%2,%3}, {%4,%5,%6,%7}, {%8,%9}, {%0,%1,%2,%3};"
        : "+f"(c[0]), "+f"(c[1]), "+f"(c[2]), "+f"(c[3])
        : "r"(a0), "r"(a1), "r"(a2), "r"(a3), "r"(b0), "r"(b1));
}

__device__ __forceinline__ float gelu_f(float x) {
    return 0.5f * x * (1.0f + erff(x * 0.70710678118654752f));
}

// ---------------- generic batched tiled GEMM (tf32 tensor-core compute) ----
// C = alpha * A @ (TRB ? B^T : B)  (+R if EPI==1, gelu if EPI==2)
// batch offset: o1 = bz/Hd, o2 = bz%Hd ; ptr += o1*s1 + o2*s2
// CSKIP: early-exit tiles fully above causal diagonal. CKLIM: truncate K to
// rowBase+BM. SWAPXY: blockIdx.x->M tile (weight-stationary L2 reuse).
// 8 warps in 2x4 grid; warp tile WM=BM/2, WN=BN/4; m16n8k8 tf32 mma.
template<int BM, int BN, int BK, bool TRB, int EPI,
         bool CSKIP = false, bool CKLIM = false, bool SWAPXY = false>
__global__ void __launch_bounds__(256, 2)
gemm_k(const float* __restrict__ A, const float* __restrict__ B,
       const float* __restrict__ R, float* __restrict__ C,
       int K, int lda, int ldb, int ldc,
       long sA1, long sA2, long sB1, long sB2, long sC1, long sC2,
       int Hd, float alpha)
{
    constexpr int THREADS = 256;
    constexpr int KV = BK / 4;
    constexpr int AR = (BM * BK) / (4 * THREADS);
    constexpr int BR = (BN * BK) / (4 * THREADS);
    constexpr int WARPS_N = 4;
    constexpr int WM = BM / 2, WN = BN / 4;
    constexpr int MT = WM / 16, NT = WN / 8;
    static_assert(AR >= 1 && BR >= 1, "tile too small");
    static_assert(MT >= 1 && NT >= 1, "warp tile too small");

    const long rowBase = (long)(SWAPXY ? blockIdx.x : blockIdx.y) * BM;
    const long colBase = (long)(SWAPXY ? blockIdx.y : blockIdx.x) * BN;

    if (CSKIP && colBase > rowBase + (BM - 1)) return;

    __shared__ __align__(16) float As[2][BK][BM + PAD_];
    __shared__ __align__(16) float Bs[2][BK][BN + PAD_];

    const long o1 = blockIdx.z / Hd;
    const long o2 = blockIdx.z % Hd;
    A += o1 * sA1 + o2 * sA2;
    B += o1 * sB1 + o2 * sB2;
    const long cOff = o1 * sC1 + o2 * sC2;
    C += cOff;
    if (EPI == 1) R += cOff;

    const int tid  = threadIdx.x;
    const int wid  = tid >> 5;
    const int lane = tid & 31;
    const int wm   = wid / WARPS_N;       // 0..1
    const int wn   = wid % WARPS_N;       // 0..3
    const int gg   = lane >> 2;           // 0..7
    const int qq   = lane & 3;            // 0..3

    float acc[MT][NT][4] = {};

    auto load_a_regs = [&](int k0, float4 (&fa)[AR]) {
        #pragma unroll
        for (int r = 0; r < AR; r++) {
            int i  = tid + r * THREADS;
            int m  = i / KV;
            int kv = i % KV;
            fa[r] = *reinterpret_cast<const float4*>(
                &A[(rowBase + m) * (long)lda + k0 + kv * 4]);
        }
    };
    auto store_a_smem = [&](int buf, const float4 (&fa)[AR]) {
        #pragma unroll
        for (int r = 0; r < AR; r++) {
            int i  = tid + r * THREADS;
            int m  = i / KV;
            int kv = i % KV;
            As[buf][kv * 4 + 0][m] = fa[r].x;
            As[buf][kv * 4 + 1][m] = fa[r].y;
            As[buf][kv * 4 + 2][m] = fa[r].z;
            As[buf][kv * 4 + 3][m] = fa[r].w;
        }
    };
    auto load_b_regs = [&](int k0, float4 (&fb)[BR]) {
        #pragma unroll
        for (int r = 0; r < BR; r++) {
            int i  = tid + r * THREADS;
            int n  = i / KV;
            int kv = i % KV;
            fb[r] = *reinterpret_cast<const float4*>(
                &B[(colBase + n) * (long)ldb + k0 + kv * 4]);
        }
    };
    auto store_b_smem = [&](int buf, const float4 (&fb)[BR]) {
        #pragma unroll
        for (int r = 0; r < BR; r++) {
            int i  = tid + r * THREADS;
            int n  = i / KV;
            int kv = i % KV;
            Bs[buf][kv * 4 + 0][n] = fb[r].x;
            Bs[buf][kv * 4 + 1][n] = fb[r].y;
            Bs[buf][kv * 4 + 2][n] = fb[r].z;
            Bs[buf][kv * 4 + 3][n] = fb[r].w;
        }
    };
    auto issue_b_cp = [&](int k0, int buf) {
        #pragma unroll
        for (int r = 0; r < BR; r++) {
            int i  = tid + r * THREADS;
            int kk = i / (BN / 4);
            int nv = i % (BN / 4);
            cp_async16(&Bs[buf][kk][nv * 4],
                       &B[(long)(k0 + kk) * ldb + colBase + nv * 4]);
        }
    };
    auto compute = [&](int buf) {
        #pragma unroll
        for (int ks = 0; ks < BK; ks += 8) {
            unsigned af[MT][4], bf[NT][2];
            #pragma unroll
            for (int mt = 0; mt < MT; mt++) {
                int m0 = wm * WM + mt * 16 + gg;
                af[mt][0] = f32_tf32(As[buf][ks + qq    ][m0    ]);
                af[mt][1] = f32_tf32(As[buf][ks + qq    ][m0 + 8]);
                af[mt][2] = f32_tf32(As[buf][ks + qq + 4][m0    ]);
                af[mt][3] = f32_tf32(As[buf][ks + qq + 4][m0 + 8]);
            }
            #pragma unroll
            for (int nt = 0; nt < NT; nt++) {
                int n0 = wn * WN + nt * 8 + gg;
                bf[nt][0] = f32_tf32(Bs[buf][ks + qq    ][n0]);
                bf[nt][1] = f32_tf32(Bs[buf][ks + qq + 4][n0]);
            }
            #pragma unroll
            for (int mt = 0; mt < MT; mt++)
                #pragma unroll
                for (int nt = 0; nt < NT; nt++)
                    mma8(acc[mt][nt], af[mt][0], af[mt][1], af[mt][2], af[mt][3],
                         bf[nt][0], bf[nt][1]);
        }
    };

    int Keff = K;
    if (CKLIM) {
        long lim = rowBase + BM;
        if (lim < Keff) Keff = (int)lim;
    }

    // ---- prologue ----
    if (!TRB) {
        issue_b_cp(0, 0);
        cp_async_commit();
    }
    {
        float4 fa[AR];
        load_a_regs(0, fa);
        store_a_smem(0, fa);
        if (TRB) {
            float4 fb[BR];
            load_b_regs(0, fb);
            store_b_smem(0, fb);
        }
    }
    if (!TRB) cp_async_wait0();
    __syncthreads();

    // ---- pipelined mainloop ----
    int buf = 0;
    const int nIter = Keff / BK;
    for (int it = 0; it < nIter; it++) {
        const bool more = (it + 1 < nIter);
        float4 fa[AR], fb[BR];
        if (more) {
            if (!TRB) {
                issue_b_cp((it + 1) * BK, buf ^ 1);
                cp_async_commit();
            }
            load_a_regs((it + 1) * BK, fa);
            if (TRB) load_b_regs((it + 1) * BK, fb);
        }
        compute(buf);
        if (more) {
            store_a_smem(buf ^ 1, fa);
            if (TRB) store_b_smem(buf ^ 1, fb);
        }
        if (!TRB) cp_async_wait0();
        __syncthreads();
        buf ^= 1;
    }

    // ---- epilogue: fragment layout, float2 stores ----
    #pragma unroll
    for (int mt = 0; mt < MT; mt++) {
        #pragma unroll
        for (int nt = 0; nt < NT; nt++) {
            long r0 = rowBase + wm * WM + mt * 16 + gg;
            long r1 = r0 + 8;
            long cb = colBase + wn * WN + nt * 8 + 2 * qq;
            float2 v0, v1;
            v0.x = acc[mt][nt][0] * alpha;
            v0.y = acc[mt][nt][1] * alpha;
            v1.x = acc[mt][nt][2] * alpha;
            v1.y = acc[mt][nt][3] * alpha;
            long i0 = r0 * (long)ldc + cb;
            long i1 = r1 * (long)ldc + cb;
            if (EPI == 1) {
                float2 a0 = *reinterpret_cast<const float2*>(&R[i0]);
                float2 a1 = *reinterpret_cast<const float2*>(&R[i1]);
                v0.x += a0.x; v0.y += a0.y;
                v1.x += a1.x; v1.y += a1.y;
            }
            if (EPI == 2) {
                v0.x = gelu_f(v0.x); v0.y = gelu_f(v0.y);
                v1.x = gelu_f(v1.x); v1.y = gelu_f(v1.y);
            }
            *reinterpret_cast<float2*>(&C[i0]) = v0;
            *reinterpret_cast<float2*>(&C[i1]) = v1;
        }
    }
}

// ---------------- fused Q/K/V projection (tf32 mma) ----------------
// Tile 128x64, BK=16. blockIdx.z = sel*32 + b*H + h.
__global__ void __launch_bounds__(256, 2)
qkv_k(const float* __restrict__ Z,
      const float* __restrict__ WQ, const float* __restrict__ WK,
      const float* __restrict__ WV,
      float* __restrict__ Q, float* __restrict__ Ko, float* __restrict__ Vo)
{
    constexpr int BM = 128, BN = 64, BK = 16;
    constexpr int THREADS = 256;
    constexpr int KV = BK / 4;
    constexpr int AR = (BM * BK) / (4 * THREADS); // 2
    constexpr int BR = (BN * BK) / (4 * THREADS); // 1
    constexpr int WARPS_N = 4;
    constexpr int WM = BM / 2, WN = BN / 4;       // 64, 16
    constexpr int MT = WM / 16, NT = WN / 8;      // 4, 2

    __shared__ __align__(16) float As[2][BK][BM + PAD_];
    __shared__ __align__(16) float Bs[2][BK][BN + PAD_];

    const int sel = blockIdx.z / (B_ * H_);
    const int bz  = blockIdx.z % (B_ * H_);
    const int b   = bz / H_;
    const int hh  = bz % H_;

    const float* A = Z + (long)b * S_ * E_;
    const float* W = (sel == 0 ? WQ : (sel == 1 ? WK : WV)) + (long)hh * E_ * HD_;
    float*       C = (sel == 0 ? Q  : (sel == 1 ? Ko : Vo)) + (long)bz * S_ * HD_;

    const int tid  = threadIdx.x;
    const int wid  = tid >> 5;
    const int lane = tid & 31;
    const int wm   = wid / WARPS_N;
    const int wn   = wid % WARPS_N;
    const int gg   = lane >> 2;
    const int qq   = lane & 3;
    const long rowBase = (long)blockIdx.y * BM;

    float acc[MT][NT][4] = {};

    auto load_a_regs = [&](int k0, float4 (&fa)[AR]) {
        #pragma unroll
        for (int r = 0; r < AR; r++) {
            int i  = tid + r * THREADS;
            int m  = i / KV;
            int kv = i % KV;
            fa[r] = *reinterpret_cast<const float4*>(
                &A[(rowBase + m) * (long)E_ + k0 + kv * 4]);
        }
    };
    auto store_a_smem = [&](int buf, const float4 (&fa)[AR]) {
        #pragma unroll
        for (int r = 0; r < AR; r++) {
            int i  = tid + r * THREADS;
            int m  = i / KV;
            int kv = i % KV;
            As[buf][kv * 4 + 0][m] = fa[r].x;
            As[buf][kv * 4 + 1][m] = fa[r].y;
            As[buf][kv * 4 + 2][m] = fa[r].z;
            As[buf][kv * 4 + 3][m] = fa[r].w;
        }
    };
    auto issue_b_cp = [&](int k0, int buf) {
        #pragma unroll
        for (int r = 0; r < BR; r++) {
            int i  = tid + r * THREADS;
            int kk = i / (BN / 4);
            int nv = i % (BN / 4);
            cp_async16(&Bs[buf][kk][nv * 4],
                       &W[(long)(k0 + kk) * HD_ + nv * 4]);
        }
    };
    auto compute = [&](int buf) {
        #pragma unroll
        for (int ks = 0; ks < BK; ks += 8) {
            unsigned af[MT][4], bf[NT][2];
            #pragma unroll
            for (int mt = 0; mt < MT; mt++) {
                int m0 = wm * WM + mt * 16 + gg;
                af[mt][0] = f32_tf32(As[buf][ks + qq    ][m0    ]);
                af[mt][1] = f32_tf32(As[buf][ks + qq    ][m0 + 8]);
                af[mt][2] = f32_tf32(As[buf][ks + qq + 4][m0    ]);
                af[mt][3] = f32_tf32(As[buf][ks + qq + 4][m0 + 8]);
            }
            #pragma unroll
            for (int nt = 0; nt < NT; nt++) {
                int n0 = wn * WN + nt * 8 + gg;
                bf[nt][0] = f32_tf32(Bs[buf][ks + qq    ][n0]);
                bf[nt][1] = f32_tf32(Bs[buf][ks + qq + 4][n0]);
            }
            #pragma unroll
            for (int mt = 0; mt < MT; mt++)
                #pragma unroll
                for (int nt = 0; nt < NT; nt++)
                    mma8(acc[mt][nt], af[mt][0], af[mt][1], af[mt][2], af[mt][3],
                         bf[nt][0], bf[nt][1]);
        }
    };

    // prologue
    issue_b_cp(0, 0);
    cp_async_commit();
    {
        float4 fa[AR];
        load_a_regs(0, fa);
        store_a_smem(0, fa);
    }
    cp_async_wait0();
    __syncthreads();

    int buf = 0;
    constexpr int nIter = E_ / BK;
    for (int it = 0; it < nIter; it++) {
        const bool more = (it + 1 < nIter);
        float4 fa[AR];
        if (more) {
            issue_b_cp((it + 1) * BK, buf ^ 1);
            cp_async_commit();
            load_a_regs((it + 1) * BK, fa);
        }
        compute(buf);
        if (more) store_a_smem(buf ^ 1, fa);
        cp_async_wait0();
        __syncthreads();
        buf ^= 1;
    }

    #pragma unroll
    for (int mt = 0; mt < MT; mt++) {
        #pragma unroll
        for (int nt = 0; nt < NT; nt++) {
            long r0 = rowBase + wm * WM + mt * 16 + gg;
            long r1 = r0 + 8;
            long cb = wn * WN + nt * 8 + 2 * qq;
            float2 v0, v1;
            v0.x = acc[mt][nt][0]; v0.y = acc[mt][nt][1];
            v1.x = acc[mt][nt][2]; v1.y = acc[mt][nt][3];
            *reinterpret_cast<float2*>(&C[r0 * (long)HD_ + cb]) = v0;
            *reinterpret_cast<float2*>(&C[r1 * (long)HD_ + cb]) = v1;
        }
    }
}

// ---------------- LayerNorm ----------------
__global__ void __launch_bounds__(256)
ln_k(const float* __restrict__ x, const float* __restrict__ g,
     const float* __restrict__ b, float* __restrict__ z)
{
    const long row = blockIdx.x;
    const float* xr = x + row * (long)E_;
    const int tid = threadIdx.x;

    float4 v = *reinterpret_cast<const float4*>(&xr[tid * 4]);
    float s  = v.x + v.y + v.z + v.w;
    float s2 = v.x * v.x + v.y * v.y + v.z * v.z + v.w * v.w;

    __shared__ float red0[8], red1[8];
    #pragma unroll
    for (int o = 16; o > 0; o >>= 1) {
        s  += __shfl_xor_sync(0xffffffffu, s,  o);
        s2 += __shfl_xor_sync(0xffffffffu, s2, o);
    }
    if ((tid & 31) == 0) { red0[tid >> 5] = s; red1[tid >> 5] = s2; }
    __syncthreads();
    if (tid == 0) {
        float ts = 0.f, ts2 = 0.f;
        #pragma unroll
        for (int i = 0; i < 8; i++) { ts += red0[i]; ts2 += red1[i]; }
        float mu  = ts / E_;
        float var = ts2 / E_ - mu * mu;
        red0[0] = mu;
        red1[0] = rsqrtf(var + 1e-5f);
    }
    __syncthreads();
    const float mu = red0[0], rstd = red1[0];
    float4 gg = *reinterpret_cast<const float4*>(&g[tid * 4]);
    float4 bb = *reinterpret_cast<const float4*>(&b[tid * 4]);
    float4 o;
    o.x = (v.x - mu) * rstd * gg.x + bb.x;
    o.y = (v.y - mu) * rstd * gg.y + bb.y;
    o.z = (v.z - mu) * rstd * gg.z + bb.z;
    o.w = (v.w - mu) * rstd * gg.w + bb.w;
    *reinterpret_cast<float4*>(&z[row * (long)E_ + tid * 4]) = o;
}

// ---------------- causal masked softmax (uniform control flow) ----------------
__global__ void __launch_bounds__(256)
softmax_k(float* __restrict__ sc)
{
    const long r = blockIdx.x;
    const int  s = (int)(r % S_);
    const int  tileEnd = ((s >> 6) + 1) << 6;
    float* row = sc + r * (long)S_;
    const int tid = threadIdx.x;
    const int t0 = tid * 4;

    float4 v;
    if (t0 <= s) {
        v = *reinterpret_cast<const float4*>(&row[t0]);
        if (t0 + 1 > s) v.y = -1e30f;
        if (t0 + 2 > s) v.z = -1e30f;
        if (t0 + 3 > s) v.w = -1e30f;
    } else {
        v = make_float4(-1e30f, -1e30f, -1e30f, -1e30f);
    }
    float mx = fmaxf(fmaxf(v.x, v.y), fmaxf(v.z, v.w));

    __shared__ float red[8];
    #pragma unroll
    for (int o = 16; o > 0; o >>= 1) mx = fmaxf(mx, __shfl_xor_sync(0xffffffffu, mx, o));
    if ((tid & 31) == 0) red[tid >> 5] = mx;
    __syncthreads();
    if (tid == 0) {
        float m = red[0];
        #pragma unroll
        for (int i = 1; i < 8; i++) m = fmaxf(m, red[i]);
        red[0] = m;
    }
    __syncthreads();
    mx = red[0];
    __syncthreads();

    v.x = (t0 + 0 > s) ? 0.f : __expf(v.x - mx);
    v.y = (t0 + 1 > s) ? 0.f : __expf(v.y - mx);
    v.z = (t0 + 2 > s) ? 0.f : __expf(v.z - mx);
    v.w = (t0 + 3 > s) ? 0.f : __expf(v.w - mx);
    float sum = v.x + v.y + v.z + v.w;
    #pragma unroll
    for (int o = 16; o > 0; o >>= 1) sum += __shfl_xor_sync(0xffffffffu, sum, o);
    if ((tid & 31) == 0) red[tid >> 5] = sum;
    __syncthreads();
    if (tid == 0) {
        float t = 0.f;
        #pragma unroll
        for (int i = 0; i < 8; i++) t += red[i];
        red[0] = t;
    }
    __syncthreads();
    const float inv = 1.0f / red[0];
    v.x *= inv; v.y *= inv; v.z *= inv; v.w *= inv;

    if (t0 < tileEnd)
        *reinterpret_cast<float4*>(&row[t0]) = v;
}

// ---------------- token + position embedding ----------------
__global__ void __launch_bounds__(256)
embed_k(const int* __restrict__ x, const float* __restrict__ emb,
        const float* __restrict__ pos, float* __restrict__ h)
{
    const long t = blockIdx.x;
    const int sPos = (int)(t % S_);
    const long tok = x[t];
    const int tid = threadIdx.x;
    float4 e = *reinterpret_cast<const float4*>(&emb[tok * E_ + tid * 4]);
    float4 p = *reinterpret_cast<const float4*>(&pos[(long)sPos * E_ + tid * 4]);
    float4 o; o.x = e.x + p.x; o.y = e.y + p.y; o.z = e.z + p.z; o.w = e.w + p.w;
    *reinterpret_cast<float4*>(&h[t * E_ + tid * 4]) = o;
}

// ---------------- host launcher ----------------
extern "C" void kernel_launch(void* const* d_in, const int* in_sizes, int n_in,
                              void* d_out, int out_size)
{
    const int*   x   = (const int*)  d_in[0];
    const float* emb = (const float*)d_in[1];
    const float* pos = (const float*)d_in[2];
    const float* Wq  = (const float*)d_in[3];
    const float* Wk  = (const float*)d_in[4];
    const float* Wv  = (const float*)d_in[5];
    const float* Wo  = (const float*)d_in[6];
    const float* g1  = (const float*)d_in[7];
    const float* b1  = (const float*)d_in[8];
    const float* g2  = (const float*)d_in[9];
    const float* b2  = (const float*)d_in[10];
    const float* W1  = (const float*)d_in[11];
    const float* W2  = (const float*)d_in[12];
    const float* gf  = (const float*)d_in[13];
    const float* bf  = (const float*)d_in[14];
    const float* Wf  = (const float*)d_in[15];
    float* out = (float*)d_out;

    float *h, *z, *q, *k, *v, *oc, *sc, *ff;
    cudaGetSymbolAddress((void**)&h,  g_h);
    cudaGetSymbolAddress((void**)&z,  g_z);
    cudaGetSymbolAddress((void**)&q,  g_q);
    cudaGetSymbolAddress((void**)&k,  g_k);
    cudaGetSymbolAddress((void**)&v,  g_v);
    cudaGetSymbolAddress((void**)&oc, g_oc);
    cudaGetSymbolAddress((void**)&sc, g_sc);
    cudaGetSymbolAddress((void**)&ff, g_ff);

    embed_k<<<T_, 256>>>(x, emb, pos, h);

    const long lyrW  = (long)H_ * E_ * HD_;
    const dim3 gQKV(1, S_ / 128, 3 * B_ * H_);
    const dim3 gSC (S_ / 128, S_ / 128, B_ * H_);
    const dim3 gAV (1, S_ / 64, B_ * H_);
    const dim3 gWO (T_ / 128, E_ / 128, 1);
    const dim3 gUP (T_ / 128, FF_ / 128, 1);
    const dim3 gDN (T_ / 128, E_ / 128, 1);
    const dim3 gLM (T_ / 128, V_ / 128, 1);

    for (int l = 0; l < L_; l++) {
        ln_k<<<T_, 256>>>(h, g1 + (long)l * E_, b1 + (long)l * E_, z);

        qkv_k<<<gQKV, 256>>>(z,
                             Wq + (long)l * lyrW, Wk + (long)l * lyrW,
                             Wv + (long)l * lyrW, q, k, v);

        gemm_k<128, 128, 16, true, 0, true, false, false><<<gSC, 256>>>(
            q, k, nullptr, sc,
            HD_, HD_, HD_, S_,
            (long)S_ * HD_, 0, (long)S_ * HD_, 0, (long)S_ * S_, 0, 1, 0.125f);

        softmax_k<<<B_ * H_ * S_, 256>>>(sc);

        gemm_k<64, 64, 16, false, 0, false, true, false><<<gAV, 256>>>(
            sc, v, nullptr, oc,
            S_, S_, HD_, E_,
            (long)H_ * S_ * S_, (long)S_ * S_,
            (long)H_ * S_ * HD_, (long)S_ * HD_,
            (long)S_ * E_, (long)HD_, H_, 1.0f);

        gemm_k<128, 128, 16, false, 1, false, false, true><<<gWO, 256>>>(
            oc, Wo + (long)l * E_ * E_, h, h,
            E_, E_, E_, E_,
            0, 0, 0, 0, 0, 0, 1, 1.0f);

        ln_k<<<T_, 256>>>(h, g2 + (long)l * E_, b2 + (long)l * E_, z);

        gemm_k<128, 128, 16, false, 2, false, false, true><<<gUP, 256>>>(
            z, W1 + (long)l * E_ * FF_, nullptr, ff,
            E_, E_, FF_, FF_,
            0, 0, 0, 0, 0, 0, 1, 1.0f);

        gemm_k<128, 128, 16, false, 1, false, false, true><<<gDN, 256>>>(
            ff, W2 + (long)l * FF_ * E_, h, h,
            FF_, FF_, E_, E_,
            0, 0, 0, 0, 0, 0, 1, 1.0f);
    }

    ln_k<<<T_, 256>>>(h, gf, bf, z);
    gemm_k<128, 128, 16, false, 0, false, false, true><<<gLM, 256>>>(
        z, Wf, nullptr, out,
        E_, E_, V_, V_,
        0, 0, 0, 0, 0, 0, 1, 1.0f);
}